// round 7
// baseline (speedup 1.0000x reference)
#include <cuda_runtime.h>
#include <math.h>

// Problem constants
#define NSIG   32768          // B*H*W signals
#define KDICT  512            // N_EMBED
#define DIMF   64             // DIM
#define HWSZ   4096           // H*W
#define REGEPS 1e-7f
#define TOPK   327            // int(32768*0.01)

// Output packing (flattened tuple, float32)
#define OUT_N    2097152      // out [8,64,64,64]
#define DIFF_OFS 2097152      // diff_enc, diff_dict
#define IDS_OFS  2097154      // ids [8,512,64,64]  (NOTE: offset % 4 == 2 -> no float4!)
#define IDS_N    16777216
#define SCAL_OFS 18874370     // num_steps, mean_D, mean_Z, norm_Z, top_percentile, num_zeros

// Device scratch (static allocation — no cudaMalloc allowed)
__device__ float  g_Dn[DIMF * KDICT];        // normalized dict [d][j]
__device__ float  g_DnT[KDICT * DIMF];       // transposed [j][d]
__device__ float  g_G[KDICT * KDICT];        // Gram
__device__ float  g_alpha0[(size_t)NSIG * KDICT];  // 64MB
__device__ double g_meanD, g_absZ, g_diff;
__device__ int    g_hist[8];

// Normalize dictionary columns; accumulate sum|Dn| for mean_D. Also init accumulators.
__global__ void prep_k(const float* __restrict__ dict) {
    if (threadIdx.x == 0) {
        g_meanD = 0.0; g_absZ = 0.0; g_diff = 0.0;
        for (int i = 0; i < 8; i++) g_hist[i] = 0;
    }
    __syncthreads();
    int j = threadIdx.x;   // 512 threads, one per atom
    float ss = 0.f;
#pragma unroll
    for (int d = 0; d < DIMF; d++) { float v = dict[d * KDICT + j]; ss += v * v; }
    float nrm = sqrtf(ss);
    double asum = 0.0;
#pragma unroll
    for (int d = 0; d < DIMF; d++) {
        float v = dict[d * KDICT + j] / nrm;
        g_Dn[d * KDICT + j] = v;
        g_DnT[j * DIMF + d] = v;
        asum += (double)fabsf(v);
    }
    atomicAdd(&g_meanD, asum);
}

// G = Dn^T Dn. 64 blocks x 512 threads; each block does 8 rows of G.
__global__ void gram_k() {
    int j = threadIdx.x;
    int i0 = blockIdx.x * 8;
    float r[DIMF];
#pragma unroll
    for (int d = 0; d < DIMF; d++) r[d] = g_Dn[d * KDICT + j];
    __shared__ float sc[8][DIMF];
    { int t = threadIdx.x; sc[t >> 6][t & 63] = g_DnT[i0 * DIMF + t]; }
    __syncthreads();
#pragma unroll
    for (int ii = 0; ii < 8; ii++) {
        float acc = 0.f;
#pragma unroll
        for (int d = 0; d < DIMF; d++) acc += r[d] * sc[ii][d];
        g_G[(i0 + ii) * KDICT + j] = acc;
    }
}

// alpha0 = Xperm @ Dn. Tile: 128 signals x 128 atoms, K=64. 256 threads, 8x8 micro.
__global__ __launch_bounds__(256) void gemm_k(const float* __restrict__ x) {
    __shared__ float Xs[DIMF][128];
    __shared__ float Ds[DIMF][128];
    int tid = threadIdx.x;
    int m0 = blockIdx.y * 128;           // 128 consecutive hw within one b
    int bb = m0 >> 12, hw0 = m0 & 4095;
    const float* xb = x + (size_t)bb * 262144 + hw0;
    for (int i = tid; i < DIMF * 32; i += 256) {       // float4 granularity
        int d = i >> 5, m4 = (i & 31) * 4;
        *(float4*)&Xs[d][m4] = *(const float4*)&xb[(size_t)d * 4096 + m4];
    }
    int n0 = blockIdx.x * 128;
    for (int i = tid; i < DIMF * 32; i += 256) {
        int d = i >> 5, n4 = (i & 31) * 4;
        *(float4*)&Ds[d][n4] = *(const float4*)&g_Dn[d * KDICT + n0 + n4];
    }
    __syncthreads();
    int tx = tid & 15, ty = tid >> 4;
    float acc[8][8];
#pragma unroll
    for (int i = 0; i < 8; i++)
#pragma unroll
        for (int j = 0; j < 8; j++) acc[i][j] = 0.f;
#pragma unroll
    for (int d = 0; d < DIMF; d++) {
        float4 a0 = *(const float4*)&Xs[d][ty * 8];
        float4 a1 = *(const float4*)&Xs[d][ty * 8 + 4];
        float4 b0 = *(const float4*)&Ds[d][tx * 8];
        float4 b1 = *(const float4*)&Ds[d][tx * 8 + 4];
        float am[8] = {a0.x, a0.y, a0.z, a0.w, a1.x, a1.y, a1.z, a1.w};
        float bn[8] = {b0.x, b0.y, b0.z, b0.w, b1.x, b1.y, b1.z, b1.w};
#pragma unroll
        for (int mm = 0; mm < 8; mm++)
#pragma unroll
            for (int nn = 0; nn < 8; nn++) acc[mm][nn] += am[mm] * bn[nn];
    }
#pragma unroll
    for (int mm = 0; mm < 8; mm++) {
        int n = m0 + ty * 8 + mm;
        float* op = &g_alpha0[(size_t)n * KDICT + n0 + tx * 8];
        *(float4*)op       = make_float4(acc[mm][0], acc[mm][1], acc[mm][2], acc[mm][3]);
        *(float4*)(op + 4) = make_float4(acc[mm][4], acc[mm][5], acc[mm][6], acc[mm][7]);
    }
}

// Main OMP kernel: one warp per signal, 8 signals/block.
// Fused: zero-fill of this block's ids region, quant out-write, diff accumulation.
// Dynamic smem: sGrow[8][4][512] (64KB) + sq[64][9] (2.25KB).
extern __shared__ float s_omp[];
__global__ __launch_bounds__(256) void omp_k(const float* __restrict__ x,
                                             float* __restrict__ out) {
    float (*sGrow)[4][KDICT] = (float (*)[4][KDICT])s_omp;
    float (*sq)[9] = (float (*)[9])(s_omp + 8 * 4 * KDICT);
    __shared__ double s_az[8];
    __shared__ int    s_cnt[8];
    __shared__ double s_red[256];

    int tid = threadIdx.x;
    int wid = tid >> 5, lane = tid & 31;
    int base_n = blockIdx.x * 8;
    int b0 = base_n >> 12, hw0 = base_n & 4095;

    // Phase 0: zero this block's ids region (512 atom-rows x 8 floats, stride 4096).
    // IDS_OFS is only 8-byte aligned -> float2 stores (never float4 here).
    {
        float2* idsz = (float2*)(out + IDS_OFS + (size_t)b0 * (KDICT * HWSZ) + hw0);
        for (int i = tid; i < 2048; i += 256) {
            int row = i >> 2, q = i & 3;               // 512 rows x 4 float2
            idsz[(size_t)row * (HWSZ / 2) + q] = make_float2(0.f, 0.f);
        }
    }

    int n = base_n + wid;
    const float* a0p = g_alpha0 + (size_t)n * KDICT;

    float a0[16], al[16];
#pragma unroll
    for (int t = 0; t < 16; t++) { a0[t] = a0p[lane + 32 * t]; al[t] = a0[t]; }

    int idxs[4]; float gam[4]; float Gs[4][4]; float rh[4];

#pragma unroll
    for (int k = 0; k < 4; k++) {
        // argmax |alpha| with first-index tie-break (j = lane + 32*t)
        float bvv = -1.f; int bj = 0;
#pragma unroll
        for (int t = 0; t < 16; t++) {
            float v = fabsf(al[t]);
            if (v > bvv) { bvv = v; bj = lane + 32 * t; }
        }
#pragma unroll
        for (int off = 16; off >= 1; off >>= 1) {
            float ov = __shfl_down_sync(0xffffffffu, bvv, off);
            int   oj = __shfl_down_sync(0xffffffffu, bj, off);
            if (ov > bvv || (ov == bvv && oj < bj)) { bvv = ov; bj = oj; }
        }
        bj = __shfl_sync(0xffffffffu, bj, 0);
        idxs[k] = bj;

        // cache G row in shared (each lane writes/reads its own 16 slots)
        const float* grow = g_G + (size_t)bj * KDICT;
#pragma unroll
        for (int t = 0; t < 16; t++) sGrow[wid][k][lane + 32 * t] = grow[lane + 32 * t];

        // new Gram-submatrix entries + rhs (uniform loads, L2 hits)
#pragma unroll
        for (int a = 0; a < 4; a++) if (a <= k) {
            float v = grow[idxs[a]];
            Gs[k][a] = v; Gs[a][k] = v;
        }
        rh[k] = a0p[bj];

        // Solve (Gs + eps I) gamma = rh, size k+1, Gaussian elimination
        float M[4][4], y[4];
#pragma unroll
        for (int i = 0; i < 4; i++) if (i <= k) {
            y[i] = rh[i];
#pragma unroll
            for (int jj = 0; jj < 4; jj++) if (jj <= k)
                M[i][jj] = Gs[i][jj] + (i == jj ? REGEPS : 0.f);
        }
#pragma unroll
        for (int c = 0; c < 4; c++) {
            if (c > k) break;
            float inv = 1.f / M[c][c];
#pragma unroll
            for (int r2 = c + 1; r2 < 4; r2++) if (r2 <= k) {
                float f = M[r2][c] * inv;
#pragma unroll
                for (int cc = c + 1; cc < 4; cc++) M[r2][cc] -= f * M[c][cc];
                y[r2] -= f * y[c];
            }
        }
#pragma unroll
        for (int r2 = 3; r2 >= 0; r2--) if (r2 <= k) {
            float s = y[r2];
#pragma unroll
            for (int cc = r2 + 1; cc < 4; cc++) if (cc <= k) s -= M[r2][cc] * gam[cc];
            gam[r2] = s / M[r2][r2];
        }

        // recompute alpha = alpha0 - sum_a gamma_a * G[idx_a,:] (skip on last iter)
        if (k < 3) {
#pragma unroll
            for (int t = 0; t < 16; t++) {
                float s = a0[t];
#pragma unroll
                for (int a = 0; a < 4; a++) if (a <= k)
                    s -= gam[a] * sGrow[wid][a][lane + 32 * t];
                al[t] = s;
            }
        }
    }

    // quant[n][d] = sum_a gam[a] * DnT[idxs[a]][d] -> smem transpose
#pragma unroll
    for (int rep = 0; rep < 2; rep++) {
        int d = lane + rep * 32;
        float s = 0.f;
#pragma unroll
        for (int a = 0; a < 4; a++) s += gam[a] * g_DnT[idxs[a] * DIMF + d];
        sq[d][wid] = s;
    }

    if (lane == 0) {
        s_az[wid] = (double)fabsf(gam[0]) + (double)fabsf(gam[1]) +
                    (double)fabsf(gam[2]) + (double)fabsf(gam[3]);
        s_cnt[wid] = (gam[0] != 0.f) + (gam[1] != 0.f) + (gam[2] != 0.f) + (gam[3] != 0.f);
    }
    __syncthreads();   // zero-fill done, sq ready, s_az/s_cnt ready

    // scatter nonzeros into ids (regions disjoint per block; zero-fill above done)
    if (lane == 0) {
        float* ids = out + IDS_OFS + (size_t)b0 * (KDICT * HWSZ) + (hw0 + wid);
        ids[(size_t)idxs[0] * HWSZ] = gam[0];
        ids[(size_t)idxs[1] * HWSZ] = gam[1];
        ids[(size_t)idxs[2] * HWSZ] = gam[2];
        ids[(size_t)idxs[3] * HWSZ] = gam[3];
    }

    // write out[b][d][hw] for this block's 8 signals + accumulate diff vs x
    double dloc = 0.0;
    for (int i = tid; i < 512; i += 256) {
        int d = i >> 3, s2 = i & 7;
        size_t gi = (size_t)b0 * 262144 + (size_t)d * 4096 + hw0 + s2;
        float v = sq[d][s2];
        out[gi] = v;
        float dd = v - x[gi];
        dloc += (double)dd * (double)dd;
    }
    s_red[tid] = dloc;
    __syncthreads();
    for (int s = 128; s > 0; s >>= 1) {
        if (tid < s) s_red[tid] += s_red[tid + s];
        __syncthreads();
    }
    if (tid == 0) {
        atomicAdd(&g_diff, s_red[0]);
        double az = 0.0; int h[5] = {0, 0, 0, 0, 0};
        for (int w = 0; w < 8; w++) { az += s_az[w]; h[s_cnt[w]]++; }
        atomicAdd(&g_absZ, az);
        for (int v = 0; v <= 4; v++) if (h[v]) atomicAdd(&g_hist[v], h[v]);
    }
}

__global__ void fin_k(float* __restrict__ out) {
    float diff = (float)(g_diff / (double)OUT_N);
    out[DIFF_OFS]     = diff;
    out[DIFF_OFS + 1] = diff;
    out[SCAL_OFS + 0] = 4.0f;  // num_steps
    out[SCAL_OFS + 1] = (float)(g_meanD / (double)(DIMF * KDICT));
    out[SCAL_OFS + 2] = (float)(g_absZ / (double)((size_t)NSIG * KDICT));
    long long nnzsum = 0;
    for (int c = 0; c <= 4; c++) nnzsum += (long long)c * g_hist[c];
    out[SCAL_OFS + 3] = (float)((double)nnzsum / (double)NSIG);
    int cum = 0; float tp = 0.f;
    for (int v = 4; v >= 0; v--) { cum += g_hist[v]; if (cum >= TOPK) { tp = (float)v; break; } }
    out[SCAL_OFS + 4] = tp;
    out[SCAL_OFS + 5] = (float)g_hist[0];
}

extern "C" void kernel_launch(void* const* d_in, const int* in_sizes, int n_in,
                              void* d_out, int out_size) {
    const float* x = (const float*)d_in[0];
    const float* dict = (const float*)d_in[1];
    if (n_in >= 2 && in_sizes[0] == DIMF * KDICT && in_sizes[1] == OUT_N) {
        const float* t = x; x = dict; dict = t;   // defensive swap
    }
    float* out = (float*)d_out;

    const int omp_smem = 8 * 4 * KDICT * 4 + 64 * 9 * 4;   // 67840 B dynamic
    cudaFuncSetAttribute(omp_k, cudaFuncAttributeMaxDynamicSharedMemorySize, omp_smem);

    prep_k<<<1, 512>>>(dict);
    gram_k<<<64, 512>>>();
    dim3 gg(KDICT / 128, NSIG / 128);
    gemm_k<<<gg, 256>>>(x);
    omp_k<<<NSIG / 8, 256, omp_smem>>>(x, out);
    fin_k<<<1, 1>>>(out);
}